// round 1
// baseline (speedup 1.0000x reference)
#include <cuda_runtime.h>

#define W 224
#define H 224
#define BC 192
#define STEPS 32
#define BANDS 8
#define ROWS_PER_BAND (H / BANDS)   // 28
#define IMG_PIX (H * W)

// Global scratch: signed histogram per (b,c). Zeroed by zero_hist each launch.
__device__ int g_hist[BC * STEPS];

// searchsorted(linspace(0,1,32), f, 'left'):
// first j with t_j >= f, where t_j = fl(j * fl(1/31)) for j<31, t_31 = 1.0.
// Start from ceil(31*f) (off by at most 1), then fix against the exact grid.
__device__ __forceinline__ int binof(float f) {
    const float step = 1.0f / 31.0f;
    int g = __float2int_ru(f * 31.0f);
    g = max(0, min(31, g));
    if (g > 0 && (float)(g - 1) * step >= f) g--;
    float tg = (g >= 31) ? 1.0f : (float)g * step;
    if (tg < f) g++;
    return g;   // in [0, 31] since f < 1 <= t_31
}

__global__ void zero_hist() {
    int i = blockIdx.x * blockDim.x + threadIdx.x;
    if (i < BC * STEPS) g_hist[i] = 0;
}

__global__ __launch_bounds__(W) void ecc_hist(const float* __restrict__ x) {
    // Per-thread private histogram columns: hist[bin][thread].
    // 224 % 32 == 0  =>  bank(hist[j][c]) = c % 32  => conflict-free for any bins.
    __shared__ int hist[STEPS][W];

    const int c    = threadIdx.x;           // column, 0..223
    const int lane = c & 31;
    const int bc   = blockIdx.x >> 3;       // image-channel index
    const int band = blockIdx.x & 7;
    const int r0   = band * ROWS_PER_BAND;
    const float* __restrict__ img = x + (long)bc * IMG_PIX;

#pragma unroll
    for (int j = 0; j < STEPS; j++) hist[j][c] = 0;
    __syncthreads();

    // Prologue: bins of row r0 (own column + right neighbor's column).
    float v = __ldg(img + r0 * W + c);
    int b  = binof(v);
    int br = __shfl_down_sync(0xffffffffu, b, 1);
    if (lane == 31 && c + 1 < W)
        br = binof(__ldg(img + r0 * W + (c + 1)));   // cross-warp neighbor

    for (int h = r0; h < r0 + ROWS_PER_BAND; h++) {
        const bool lastRow = (h == H - 1);
        int nb = 0;
        if (!lastRow)
            nb = binof(__ldg(img + (h + 1) * W + c));
        int nbr = __shfl_down_sync(0xffffffffu, nb, 1);
        if (!lastRow && lane == 31 && c + 1 < W)
            nbr = binof(__ldg(img + (h + 1) * W + (c + 1)));

        // Cell updates for pixel (h, c):
        //   vertex  +1 @ b
        //   h-edge  -1 @ max(b, br)            (exists if c < W-1)
        //   v-edge  -1 @ max(b, nb)            (exists if h < H-1)
        //   square  +1 @ max(b, br, nb, nbr)   (exists if both)
        hist[b][c] += 1;
        const bool hasR = (c < W - 1);
        const int bR = max(b, br);
        if (hasR) hist[bR][c] -= 1;
        if (!lastRow) {
            const int bD = max(b, nb);
            hist[bD][c] -= 1;
            if (hasR) {
                const int b4 = max(bR, max(nb, nbr));
                hist[b4][c] += 1;
            }
        }

        b = nb; br = nbr;   // row h+1 becomes current
    }
    __syncthreads();

    // Block reduction: 7 warps, each owns bins j = wid, wid+7, ...
    const int wid = c >> 5;
    for (int j = wid; j < STEPS; j += (W / 32)) {
        int sum = 0;
#pragma unroll
        for (int t = lane; t < W; t += 32) sum += hist[j][t];
#pragma unroll
        for (int o = 16; o; o >>= 1) sum += __shfl_down_sync(0xffffffffu, sum, o);
        if (lane == 0) atomicAdd(&g_hist[bc * STEPS + j], sum);
    }
}

__global__ void finalize(float* __restrict__ out) {
    int i = blockIdx.x * blockDim.x + threadIdx.x;
    if (i >= BC * STEPS) return;
    const int base = i & ~(STEPS - 1);   // bc * 32
    const int j    = i & (STEPS - 1);
    int s = 0;
    for (int k = 0; k <= j; k++) s += g_hist[base + k];
    out[i] = (float)s;
}

extern "C" void kernel_launch(void* const* d_in, const int* in_sizes, int n_in,
                              void* d_out, int out_size) {
    const float* x = (const float*)d_in[0];
    float* out = (float*)d_out;
    (void)in_sizes; (void)n_in; (void)out_size;

    zero_hist<<<(BC * STEPS + 255) / 256, 256>>>();
    ecc_hist<<<BC * BANDS, W>>>(x);
    finalize<<<(BC * STEPS + 255) / 256, 256>>>(out);
}